// round 9
// baseline (speedup 1.0000x reference)
#include <cuda_runtime.h>
#include <cuda_bf16.h>
#include <cstdint>

// ---------------- problem constants ----------------
#define NXC 256
#define NYC 256
#define BC  8
#define CO  32

__device__ __constant__ float c_VX    = 0.3125f;          // 1/3.2
__device__ __constant__ float c_VY    = 0.3125f;
__device__ __constant__ float c_XOFF  = -39.84375f;       // VX/2 + X_MIN
__device__ __constant__ float c_YOFF  = -19.84375f;       // VY/2 + Y_MIN

// ---------------- scratch (device globals, zero-init at load) ----------------
__device__ float g_featA[60000 * 64];
__device__ float g_featR[80000 * 64];
__device__ int   g_ownerA[BC * NYC * NXC];
__device__ int   g_ownerR[BC * NYC * NXC];

// ---------------- packed f32x2 helpers (FFMA2 via PTX, sm_100+) -------------
typedef unsigned long long ull;

__device__ __forceinline__ ull pack2(float lo, float hi) {
    ull r; asm("mov.b64 %0, {%1,%2};" : "=l"(r) : "f"(lo), "f"(hi)); return r;
}
__device__ __forceinline__ void fma2(ull& d, ull a, ull b) {
    asm("fma.rn.f32x2 %0, %1, %2, %3;" : "=l"(d) : "l"(a), "l"(b), "l"(d));
}
__device__ __forceinline__ float2 unpack2(ull v) {
    float2 r; asm("mov.b64 {%0,%1}, %2;" : "=f"(r.x), "=f"(r.y) : "l"(v)); return r;
}
__device__ __forceinline__ void red_add_v2(float* p, float x, float y) {
    asm volatile("red.global.add.v2.f32 [%0], {%1,%2};" :: "l"(p), "f"(x), "f"(y) : "memory");
}

// ============================================================================
// VFE warp body (algebraically folded). ONE WARP per pillar.
// Lane owns output-dim pair d = (2*lane, 2*lane+1).
//   dot_p = sum_{c<C} v_pc * we_c + K
//   we0=w0+wC+wC3, we1=w1+wC1+wC4, we2=w2+wC2 (folded cluster/center channels)
//   K = b - m·(wC,wC1,wC2) - xo*wC3 - yo*wC4
// out = max(0, max_{p<np} dot_p). Owner resolution (last idx wins) fused.
// ============================================================================
template <int P, int C>
__device__ __forceinline__ void vfe_warp(
    const float* __restrict__ voxels, const int* __restrict__ coors,
    const int* __restrict__ nump, const float* __restrict__ W,
    const float* __restrict__ bias, float* __restrict__ outf,
    int* __restrict__ owner, int i, float* __restrict__ sraw)
{
    int lane = threadIdx.x & 31;
    const float* v = voxels + (size_t)i * (P * C);
#pragma unroll
    for (int k = lane; k < P * C; k += 32) sraw[k] = v[k];
    int np = nump[i];                 // 1..P
    __syncwarp();

    // mean over first np points via bfly reduction (P <= 32)
    float sx = 0.f, sy = 0.f, sz = 0.f;
    if (lane < np) { sx = sraw[lane * C]; sy = sraw[lane * C + 1]; sz = sraw[lane * C + 2]; }
#pragma unroll
    for (int o = 16; o; o >>= 1) {
        sx += __shfl_xor_sync(0xffffffffu, sx, o);
        sy += __shfl_xor_sync(0xffffffffu, sy, o);
        sz += __shfl_xor_sync(0xffffffffu, sz, o);
    }
    float inv = 1.f / (float)np;
    float mx = sx * inv, my = sy * inv, mz = sz * inv;

    int cb = coors[3 * i], cy = coors[3 * i + 1], cx = coors[3 * i + 2];
    if (lane == 0) atomicMax(&owner[(cb * NYC + cy) * NXC + cx], i + 1);
    float xo = (float)cx * c_VX + c_XOFF;
    float yo = (float)cy * c_VY + c_YOFF;

    // per-lane weight column pairs (L1-resident)
    float2 wc[C + 5];
#pragma unroll
    for (int c = 0; c < C + 5; ++c) wc[c] = *(const float2*)(W + c * 64 + 2 * lane);
    float2 bs = *(const float2*)(bias + 2 * lane);

    float2 wef[C];
#pragma unroll
    for (int c = 0; c < C; ++c) wef[c] = wc[c];
    wef[0].x += wc[C].x + wc[C + 3].x;  wef[0].y += wc[C].y + wc[C + 3].y;
    wef[1].x += wc[C + 1].x + wc[C + 4].x;  wef[1].y += wc[C + 1].y + wc[C + 4].y;
    wef[2].x += wc[C + 2].x;  wef[2].y += wc[C + 2].y;
    ull we2[C];
#pragma unroll
    for (int c = 0; c < C; ++c) we2[c] = pack2(wef[c].x, wef[c].y);

    float Kx = bs.x - mx * wc[C].x - my * wc[C + 1].x - mz * wc[C + 2].x
                    - xo * wc[C + 3].x - yo * wc[C + 4].x;
    float Ky = bs.y - mx * wc[C].y - my * wc[C + 1].y - mz * wc[C + 2].y
                    - xo * wc[C + 3].y - yo * wc[C + 4].y;
    ull K2 = pack2(Kx, Ky);

    float a0 = 0.f, a1 = 0.f, b0 = 0.f, b1 = 0.f;
    int p = 0;
    for (; p + 2 <= np; p += 2) {
        ull d2 = K2, e2 = K2;
        const float* r0 = &sraw[p * C];
#pragma unroll
        for (int c = 0; c < C; ++c) {
            float fa = r0[c], fb = r0[C + c];
            fma2(d2, pack2(fa, fa), we2[c]);
            fma2(e2, pack2(fb, fb), we2[c]);
        }
        float2 u = unpack2(d2), w = unpack2(e2);
        a0 = fmaxf(a0, u.x); a1 = fmaxf(a1, u.y);
        b0 = fmaxf(b0, w.x); b1 = fmaxf(b1, w.y);
    }
    if (p < np) {
        ull d2 = K2;
        const float* r0 = &sraw[p * C];
#pragma unroll
        for (int c = 0; c < C; ++c) { float fa = r0[c]; fma2(d2, pack2(fa, fa), we2[c]); }
        float2 u = unpack2(d2);
        a0 = fmaxf(a0, u.x); a1 = fmaxf(a1, u.y);
    }
    float2 res = make_float2(fmaxf(a0, b0), fmaxf(a1, b1));
    *(float2*)(outf + (size_t)i * 64 + 2 * lane) = res;
}

// ============================================================================
// Fused prep kernel: [init blocks | warp-per-pillar VFE (agent then rg)]
// ============================================================================
#define INITB 2048

__global__ __launch_bounds__(256) void prep_kernel(
    const float* voxA, const int* cA, const int* npA, const float* wA, const float* bA,
    const float* voxR, const int* cR, const int* npR, const float* wR, const float* bR,
    float* featA, float* featR, int* ownerA, int* ownerR, int Ma, int Mr,
    float4* out4, const float* __restrict__ cb, int n4)
{
    __shared__ __align__(16) float sraw[8][104];

    int bid = blockIdx.x;
    if (bid < INITB) {
        for (int i = bid * 256 + threadIdx.x; i < n4; i += INITB * 256) {
            int c = (i * 4) & (CO - 1);
            out4[i] = make_float4(cb[c], cb[c + 1], cb[c + 2], cb[c + 3]);
        }
        return;
    }
    int warp = threadIdx.x >> 5;
    int pi = (bid - INITB) * 8 + warp;
    if (pi < Ma) {
        vfe_warp<20, 5>(voxA, cA, npA, wA, bA, featA, ownerA, pi, sraw[warp]);
    } else if (pi < Ma + Mr) {
        vfe_warp<32, 3>(voxR, cR, npR, wR, bR, featR, ownerR, pi - Ma, sraw[warp]);
    }
}

// ============================================================================
// Fused sparse scatter-conv, all 9 taps, co-pair packed FFMA2.
// Block 256 thr (8 warps), T=8 pillars/warp. Lane: c2=2*(lane&15) co-pair,
// h=lane>>4 pillar parity (owns pillars t with t&1==h).
// Weight smem layout (per ci = 288 floats):
//   swp[ci][j=0..3][co2=0..15][4] = {w(2j,c2),w(2j,c2+1),w(2j+1,c2),w(2j+1,c2+1)}
//      -> one LDS.128 yields packed pairs for TWO taps            (64 KB)
//   sws[ci][co 0..31]            = tap 8                          ( 8 KB)
// Features staged PRE-DUPLICATED as (f,f) ull: sfd[warp][ci][t pad 9] (36 KB)
// Per ci: 4 LDS.128 + 1 LDS.64 (w) + 4 LDS.64 bcast (f) + 36 FFMA2 = 45 issues.
// Epilogue: red.global.add.v2.f32.
// ============================================================================
#define SW_PAIR_FLOATS (64 * 256)                 // 16384 floats = 64 KB
#define SW_SING_FLOATS (64 * 32)                  //  2048 floats =  8 KB
#define SFD_ULLS       (8 * 64 * 9)               //  4608 ull    = 36 KB
#define CONV_SMEM ((SW_PAIR_FLOATS + SW_SING_FLOATS) * 4 + SFD_ULLS * 8)

__global__ __launch_bounds__(256, 2) void conv_kernel(
    const float* __restrict__ fA, const int* __restrict__ cA, const int* __restrict__ oA, int Ma,
    const float* __restrict__ fR, const int* __restrict__ cR, const int* __restrict__ oR, int Mr,
    const float* __restrict__ conv_w, float* __restrict__ out, int Ga, int Gr)
{
    extern __shared__ __align__(16) float smem[];
    float* swp = smem;                                   // paired taps 0..7
    float* sws = smem + SW_PAIR_FLOATS;                  // tap 8
    ull*   sfd = (ull*)(smem + SW_PAIR_FLOATS + SW_SING_FLOATS);

    bool isA = (int)blockIdx.x < Ga;
    const float* feats = isA ? fA : fR;
    const int*   coors = isA ? cA : cR;
    const int*   owner = isA ? oA : oR;
    int M      = isA ? Ma : Mr;
    int ci_off = isA ? 0 : 64;
    int nblk   = isA ? Ga : Gr;
    int blk    = isA ? blockIdx.x : blockIdx.x - Ga;

    int tid = threadIdx.x;
    for (int k = tid; k < 9 * 64 * 32; k += 256) {
        int tap = k >> 11, rem = k & 2047;
        int ci = rem >> 5, co = rem & 31;
        float val = conv_w[(tap * 128 + ci_off + ci) * 32 + co];
        if (tap < 8)
            swp[ci * 256 + (tap >> 1) * 64 + (co >> 1) * 4 + (tap & 1) * 2 + (co & 1)] = val;
        else
            sws[ci * 32 + co] = val;
    }
    __syncthreads();

    int warp = tid >> 5, lane = tid & 31;
    int h  = lane >> 4;
    int c2 = (lane & 15) * 2;
    ull* sfw = sfd + warp * (64 * 9);

    int stride = nblk * 8 * 8;
    for (int base = (blk * 8 + warp) * 8; base < M; base += stride) {
        int myb[4], myy[4], myx[4]; bool myv[4];
#pragma unroll
        for (int t = 0; t < 8; ++t) {
            int i = base + t;
            float f0 = 0.f, f1 = 0.f; int b = 0, y = 0, x = 0; bool v = false;
            if (i < M) {
                b = coors[3 * i]; y = coors[3 * i + 1]; x = coors[3 * i + 2];
                v = (owner[(b * NYC + y) * NXC + x] == i + 1);
                f0 = feats[(size_t)i * 64 + lane];
                f1 = feats[(size_t)i * 64 + 32 + lane];
            }
            sfw[lane * 9 + t]        = pack2(f0, f0);
            sfw[(lane + 32) * 9 + t] = pack2(f1, f1);
            if ((t & 1) == h) {
                int tp = t >> 1;
                myb[tp] = b; myy[tp] = y; myx[tp] = x; myv[tp] = v;
            }
        }
        __syncwarp();

        ull acc[4][9];
#pragma unroll
        for (int tp = 0; tp < 4; ++tp)
#pragma unroll
            for (int k = 0; k < 9; ++k) acc[tp][k] = 0ULL;

        const float* prow = swp + c2 * 2;
        const ull*   srow = (const ull*)(sws + c2);
#pragma unroll 4
        for (int ci = 0; ci < 64; ++ci) {
            ull f2[4];
#pragma unroll
            for (int tp = 0; tp < 4; ++tp) f2[tp] = sfw[ci * 9 + 2 * tp + h];
#pragma unroll
            for (int j = 0; j < 4; ++j) {
                float4 w4 = *(const float4*)(prow + ci * 256 + j * 64);
                ull wa = pack2(w4.x, w4.y);      // tap 2j   (register alias)
                ull wb = pack2(w4.z, w4.w);      // tap 2j+1
#pragma unroll
                for (int tp = 0; tp < 4; ++tp) {
                    fma2(acc[tp][2 * j],     f2[tp], wa);
                    fma2(acc[tp][2 * j + 1], f2[tp], wb);
                }
            }
            ull w8 = srow[ci * 16];              // sws + ci*32 floats
#pragma unroll
            for (int tp = 0; tp < 4; ++tp) fma2(acc[tp][8], f2[tp], w8);
        }

#pragma unroll
        for (int tp = 0; tp < 4; ++tp) {
            if (!myv[tp]) continue;
#pragma unroll
            for (int ky = 0; ky < 3; ++ky) {
                int oy = myy[tp] + 1 - ky;
                if ((unsigned)oy >= NYC) continue;
                size_t rb = ((size_t)myb[tp] * NYC + oy) * NXC;
#pragma unroll
                for (int kx = 0; kx < 3; ++kx) {
                    int ox = myx[tp] + 1 - kx;
                    if ((unsigned)ox >= NXC) continue;
                    float2 v2 = unpack2(acc[tp][ky * 3 + kx]);
                    red_add_v2(out + (rb + ox) * 32 + c2, v2.x, v2.y);
                }
            }
        }
        __syncwarp();
    }
}

// ============================================================================
// launch
// ============================================================================
extern "C" void kernel_launch(void* const* d_in, const int* in_sizes, int n_in,
                              void* d_out, int out_size)
{
    const float* voxels_agent = (const float*)d_in[0];
    const int*   coors_agent  = (const int*)  d_in[1];
    const int*   np_agent     = (const int*)  d_in[2];
    const float* voxels_rg    = (const float*)d_in[3];
    const int*   coors_rg     = (const int*)  d_in[4];
    const int*   np_rg        = (const int*)  d_in[5];
    const float* w_agent      = (const float*)d_in[6];
    const float* b_agent      = (const float*)d_in[7];
    const float* w_rg         = (const float*)d_in[8];
    const float* b_rg         = (const float*)d_in[9];
    const float* conv_w       = (const float*)d_in[10];
    const float* conv_b       = (const float*)d_in[11];

    int Ma = in_sizes[0] / (20 * 5);
    int Mr = in_sizes[3] / (32 * 3);
    float* out = (float*)d_out;

    float *featA, *featR;
    int   *ownerA, *ownerR;
    cudaGetSymbolAddress((void**)&featA,  g_featA);
    cudaGetSymbolAddress((void**)&featR,  g_featR);
    cudaGetSymbolAddress((void**)&ownerA, g_ownerA);
    cudaGetSymbolAddress((void**)&ownerR, g_ownerR);

    // 1) fused init + warp-per-pillar VFE + owner resolution
    int n4 = out_size / 4;
    int vfe_blocks = (Ma + Mr + 7) / 8;
    prep_kernel<<<INITB + vfe_blocks, 256>>>(
        voxels_agent, coors_agent, np_agent, w_agent, b_agent,
        voxels_rg, coors_rg, np_rg, w_rg, b_rg,
        featA, featR, ownerA, ownerR, Ma, Mr,
        (float4*)out, conv_b, n4);

    // 2) fused sparse scatter-conv (both sets, all 9 taps)
    cudaFuncSetAttribute(conv_kernel, cudaFuncAttributeMaxDynamicSharedMemorySize, CONV_SMEM);
    int total = Ma + Mr;
    int G = 296;                               // 2 CTAs/SM on 148 SMs
    int Ga = (int)((long long)G * Ma / total);
    if (Ga < 1) Ga = 1; if (Ga > G - 1) Ga = G - 1;
    int Gr = G - Ga;
    conv_kernel<<<G, 256, CONV_SMEM>>>(featA, coors_agent, ownerA, Ma,
                                       featR, coors_rg,    ownerR, Mr,
                                       conv_w, out, Ga, Gr);
}

// round 10
// speedup vs baseline: 1.1129x; 1.1129x over previous
#include <cuda_runtime.h>
#include <cuda_bf16.h>
#include <cstdint>

// ---------------- problem constants ----------------
#define NXC 256
#define NYC 256
#define BC  8
#define CO  32

__device__ __constant__ float c_VX    = 0.3125f;          // 1/3.2
__device__ __constant__ float c_VY    = 0.3125f;
__device__ __constant__ float c_XOFF  = -39.84375f;       // VX/2 + X_MIN
__device__ __constant__ float c_YOFF  = -19.84375f;       // VY/2 + Y_MIN

// ---------------- scratch (device globals, zero-init at load) ----------------
__device__ float g_featA[60000 * 64];
__device__ float g_featR[80000 * 64];
__device__ int   g_ownerA[BC * NYC * NXC];
__device__ int   g_ownerR[BC * NYC * NXC];

// ---------------- packed f32x2 helpers (FFMA2 via PTX, sm_100+) -------------
typedef unsigned long long ull;

__device__ __forceinline__ ull pack2(float lo, float hi) {
    ull r; asm("mov.b64 %0, {%1,%2};" : "=l"(r) : "f"(lo), "f"(hi)); return r;
}
__device__ __forceinline__ void fma2(ull& d, ull a, ull b) {
    asm("fma.rn.f32x2 %0, %1, %2, %3;" : "=l"(d) : "l"(a), "l"(b), "l"(d));
}
__device__ __forceinline__ float2 unpack2(ull v) {
    float2 r; asm("mov.b64 {%0,%1}, %2;" : "=f"(r.x), "=f"(r.y) : "l"(v)); return r;
}
__device__ __forceinline__ void red_add_v2(float* p, float x, float y) {
    asm volatile("red.global.add.v2.f32 [%0], {%1,%2};" :: "l"(p), "f"(x), "f"(y) : "memory");
}

// ============================================================================
// VFE multi-pillar warp body. ONE WARP handles NP consecutive pillars; folded
// weights are built ONCE per warp in registers.
// Lane owns output-dim pair d = (2*lane, 2*lane+1).
//   dot_p = sum_{c<C} v_pc * we_c + K     (cluster/center channels folded)
// out = max(0, max_{p<np} dot_p). Owner resolution (last idx wins) fused.
// Raw points staged in smem PRE-DUPLICATED as (f,f) ull -> compute loop is
// pure LDS.64 + FFMA2 per channel.
// ============================================================================
template <int P, int C, int NP>
__device__ __forceinline__ void vfe_multi(
    const float* __restrict__ voxels, const int* __restrict__ coors,
    const int* __restrict__ nump, const float* __restrict__ W,
    const float* __restrict__ bias, float* __restrict__ outf,
    int* __restrict__ owner, int base, int M, ull* __restrict__ sraw)
{
    int lane = threadIdx.x & 31;

    // ---- per-warp weight fold (amortized over NP pillars) ----
    float2 wc[5];                       // channels C..C+4
#pragma unroll
    for (int c = 0; c < 5; ++c) wc[c] = *(const float2*)(W + (C + c) * 64 + 2 * lane);
    float2 bs = *(const float2*)(bias + 2 * lane);

    ull we2[C];
#pragma unroll
    for (int c = 0; c < C; ++c) {
        float2 w = *(const float2*)(W + c * 64 + 2 * lane);
        if (c == 0) { w.x += wc[0].x + wc[3].x;  w.y += wc[0].y + wc[3].y; }
        if (c == 1) { w.x += wc[1].x + wc[4].x;  w.y += wc[1].y + wc[4].y; }
        if (c == 2) { w.x += wc[2].x;            w.y += wc[2].y; }
        we2[c] = pack2(w.x, w.y);
    }

    const float* srawf = (const float*)sraw;   // lo half of each dup pair

#pragma unroll 1
    for (int t = 0; t < NP; ++t) {
        int i = base + t;                 // warp-uniform
        if (i >= M) return;

        const float* v = voxels + (size_t)i * (P * C);
#pragma unroll
        for (int k = lane; k < P * C; k += 32) { float f = v[k]; sraw[k] = pack2(f, f); }
        int np = nump[i];                 // 1..P
        __syncwarp();

        // mean over first np points (P <= 32) via bfly reduction
        float sx = 0.f, sy = 0.f, sz = 0.f;
        if (lane < np) {
            sx = srawf[(lane * C + 0) * 2];
            sy = srawf[(lane * C + 1) * 2];
            sz = srawf[(lane * C + 2) * 2];
        }
#pragma unroll
        for (int o = 16; o; o >>= 1) {
            sx += __shfl_xor_sync(0xffffffffu, sx, o);
            sy += __shfl_xor_sync(0xffffffffu, sy, o);
            sz += __shfl_xor_sync(0xffffffffu, sz, o);
        }
        float inv = 1.f / (float)np;
        float mx = sx * inv, my = sy * inv, mz = sz * inv;

        int cb = coors[3 * i], cy = coors[3 * i + 1], cx = coors[3 * i + 2];
        if (lane == 0) atomicMax(&owner[(cb * NYC + cy) * NXC + cx], i + 1);
        float xo = (float)cx * c_VX + c_XOFF;
        float yo = (float)cy * c_VY + c_YOFF;

        float Kx = bs.x - mx * wc[0].x - my * wc[1].x - mz * wc[2].x
                        - xo * wc[3].x - yo * wc[4].x;
        float Ky = bs.y - mx * wc[0].y - my * wc[1].y - mz * wc[2].y
                        - xo * wc[3].y - yo * wc[4].y;
        ull K2 = pack2(Kx, Ky);

        float a0 = 0.f, a1 = 0.f, b0 = 0.f, b1 = 0.f;
        int p = 0;
        for (; p + 2 <= np; p += 2) {
            ull d2 = K2, e2 = K2;
            const ull* r0 = &sraw[p * C];
#pragma unroll
            for (int c = 0; c < C; ++c) {
                fma2(d2, r0[c],     we2[c]);
                fma2(e2, r0[C + c], we2[c]);
            }
            float2 u = unpack2(d2), w = unpack2(e2);
            a0 = fmaxf(a0, u.x); a1 = fmaxf(a1, u.y);
            b0 = fmaxf(b0, w.x); b1 = fmaxf(b1, w.y);
        }
        if (p < np) {
            ull d2 = K2;
            const ull* r0 = &sraw[p * C];
#pragma unroll
            for (int c = 0; c < C; ++c) fma2(d2, r0[c], we2[c]);
            float2 u = unpack2(d2);
            a0 = fmaxf(a0, u.x); a1 = fmaxf(a1, u.y);
        }
        float2 res = make_float2(fmaxf(a0, b0), fmaxf(a1, b1));
        *(float2*)(outf + (size_t)i * 64 + 2 * lane) = res;
        __syncwarp();                     // protect sraw before next pillar's staging
    }
}

// ============================================================================
// Fused prep kernel: [init blocks | VFE agent blocks | VFE rg blocks]
// 256 threads = 8 warps; each warp handles NPIL consecutive pillars.
// ============================================================================
#define INITB 1024
#define NPIL  8

__global__ __launch_bounds__(256) void prep_kernel(
    const float* voxA, const int* cA, const int* npA, const float* wA, const float* bA,
    const float* voxR, const int* cR, const int* npR, const float* wR, const float* bR,
    float* featA, float* featR, int* ownerA, int* ownerR, int Ma, int Mr, int blkA,
    float4* out4, const float* __restrict__ cb, int n4)
{
    __shared__ __align__(16) ull sraw[8][100];   // max P*C = 100

    int bid = blockIdx.x;
    if (bid < INITB) {
        for (int i = bid * 256 + threadIdx.x; i < n4; i += INITB * 256) {
            int c = (i * 4) & (CO - 1);
            out4[i] = make_float4(cb[c], cb[c + 1], cb[c + 2], cb[c + 3]);
        }
        return;
    }
    int warp = threadIdx.x >> 5;
    int rel = bid - INITB;
    if (rel < blkA) {
        int base = (rel * 8 + warp) * NPIL;
        vfe_multi<20, 5, NPIL>(voxA, cA, npA, wA, bA, featA, ownerA, base, Ma, sraw[warp]);
    } else {
        int base = ((rel - blkA) * 8 + warp) * NPIL;
        vfe_multi<32, 3, NPIL>(voxR, cR, npR, wR, bR, featR, ownerR, base, Mr, sraw[warp]);
    }
}

// ============================================================================
// Fused sparse scatter-conv (R6 structure), all 9 taps, co-pair packed FFMA2.
// Block 256 thr (8 warps), T=8 pillars/warp. Lane: c2=2*(lane&15) co-pair,
// h=lane>>4 pillar parity. Weights: sw[tap][ci][co] 9 LDS.64/ci (distinct,
// conflict-free). Features: sf[warp][ci][t] stride 9 floats (staging STS.32
// conflict-free, reads broadcast LDS.32). Epilogue: red.global.add.v2.f32.
// smem: 72 KB weights + 18 KB features = 90 KB -> 2 CTA/SM.
// ============================================================================
#define CONV_SMEM (9 * 64 * 32 * 4 + 8 * 64 * 9 * 4)

__global__ __launch_bounds__(256, 2) void conv_kernel(
    const float* __restrict__ fA, const int* __restrict__ cA, const int* __restrict__ oA, int Ma,
    const float* __restrict__ fR, const int* __restrict__ cR, const int* __restrict__ oR, int Mr,
    const float* __restrict__ conv_w, float* __restrict__ out, int Ga, int Gr)
{
    extern __shared__ __align__(16) float smem[];
    float* sw = smem;                 // [tap][ci][co]
    float* sf = smem + 9 * 64 * 32;   // [warp][ci][t(stride 9)]

    bool isA = (int)blockIdx.x < Ga;
    const float* feats = isA ? fA : fR;
    const int*   coors = isA ? cA : cR;
    const int*   owner = isA ? oA : oR;
    int M      = isA ? Ma : Mr;
    int ci_off = isA ? 0 : 64;
    int nblk   = isA ? Ga : Gr;
    int blk    = isA ? blockIdx.x : blockIdx.x - Ga;

    int tid = threadIdx.x;
    for (int k = tid; k < 9 * 64 * 32; k += 256) {
        int tap = k >> 11, rem = k & 2047;              // rem = ci*32+co
        sw[k] = conv_w[(tap * 128 + ci_off + (rem >> 5)) * 32 + (rem & 31)];
    }
    __syncthreads();

    int warp = tid >> 5, lane = tid & 31;
    int h = lane >> 4;                 // pillar parity this lane owns
    int c2 = (lane & 15) * 2;          // co pair
    float* sfw = sf + warp * (64 * 9);

    int stride = nblk * 8 * 8;         // blocks * warps * T
    for (int base = (blk * 8 + warp) * 8; base < M; base += stride) {
        int myb[4], myy[4], myx[4]; bool myv[4];
#pragma unroll
        for (int t = 0; t < 8; ++t) {
            int i = base + t;
            float f0 = 0.f, f1 = 0.f; int b = 0, y = 0, x = 0; bool v = false;
            if (i < M) {
                b = coors[3 * i]; y = coors[3 * i + 1]; x = coors[3 * i + 2];
                v = (owner[(b * NYC + y) * NXC + x] == i + 1);
                f0 = feats[(size_t)i * 64 + lane];
                f1 = feats[(size_t)i * 64 + 32 + lane];
            }
            sfw[lane * 9 + t]        = f0;   // stride 9 -> conflict-free
            sfw[(lane + 32) * 9 + t] = f1;
            if ((t & 1) == h) {
                int tp = t >> 1;
                myb[tp] = b; myy[tp] = y; myx[tp] = x; myv[tp] = v;
            }
        }
        __syncwarp();

        ull acc[4][9];
#pragma unroll
        for (int tp = 0; tp < 4; ++tp)
#pragma unroll
            for (int k = 0; k < 9; ++k) acc[tp][k] = 0ULL;

#pragma unroll 4
        for (int ci = 0; ci < 64; ++ci) {
            ull f2[4];
#pragma unroll
            for (int tp = 0; tp < 4; ++tp) {
                float fv = sfw[ci * 9 + 2 * tp + h];
                f2[tp] = pack2(fv, fv);
            }
            const float* wrow = sw + ci * 32 + c2;
#pragma unroll
            for (int tap = 0; tap < 9; ++tap) {
                ull w2 = *reinterpret_cast<const ull*>(wrow + tap * 2048);  // LDS.64 pair
#pragma unroll
                for (int tp = 0; tp < 4; ++tp) fma2(acc[tp][tap], f2[tp], w2);
            }
        }

#pragma unroll
        for (int tp = 0; tp < 4; ++tp) {
            if (!myv[tp]) continue;
#pragma unroll
            for (int ky = 0; ky < 3; ++ky) {
                int oy = myy[tp] + 1 - ky;
                if ((unsigned)oy >= NYC) continue;
                size_t rb = ((size_t)myb[tp] * NYC + oy) * NXC;
#pragma unroll
                for (int kx = 0; kx < 3; ++kx) {
                    int ox = myx[tp] + 1 - kx;
                    if ((unsigned)ox >= NXC) continue;
                    float2 v2 = unpack2(acc[tp][ky * 3 + kx]);
                    red_add_v2(out + (rb + ox) * 32 + c2, v2.x, v2.y);
                }
            }
        }
        __syncwarp();
    }
}

// ============================================================================
// launch
// ============================================================================
extern "C" void kernel_launch(void* const* d_in, const int* in_sizes, int n_in,
                              void* d_out, int out_size)
{
    const float* voxels_agent = (const float*)d_in[0];
    const int*   coors_agent  = (const int*)  d_in[1];
    const int*   np_agent     = (const int*)  d_in[2];
    const float* voxels_rg    = (const float*)d_in[3];
    const int*   coors_rg     = (const int*)  d_in[4];
    const int*   np_rg        = (const int*)  d_in[5];
    const float* w_agent      = (const float*)d_in[6];
    const float* b_agent      = (const float*)d_in[7];
    const float* w_rg         = (const float*)d_in[8];
    const float* b_rg         = (const float*)d_in[9];
    const float* conv_w       = (const float*)d_in[10];
    const float* conv_b       = (const float*)d_in[11];

    int Ma = in_sizes[0] / (20 * 5);
    int Mr = in_sizes[3] / (32 * 3);
    float* out = (float*)d_out;

    float *featA, *featR;
    int   *ownerA, *ownerR;
    cudaGetSymbolAddress((void**)&featA,  g_featA);
    cudaGetSymbolAddress((void**)&featR,  g_featR);
    cudaGetSymbolAddress((void**)&ownerA, g_ownerA);
    cudaGetSymbolAddress((void**)&ownerR, g_ownerR);

    // 1) fused init + multi-pillar VFE + owner resolution
    int n4 = out_size / 4;
    int blkA = (Ma + 8 * NPIL - 1) / (8 * NPIL);
    int blkR = (Mr + 8 * NPIL - 1) / (8 * NPIL);
    prep_kernel<<<INITB + blkA + blkR, 256>>>(
        voxels_agent, coors_agent, np_agent, w_agent, b_agent,
        voxels_rg, coors_rg, np_rg, w_rg, b_rg,
        featA, featR, ownerA, ownerR, Ma, Mr, blkA,
        (float4*)out, conv_b, n4);

    // 2) fused sparse scatter-conv (both sets, all 9 taps)
    cudaFuncSetAttribute(conv_kernel, cudaFuncAttributeMaxDynamicSharedMemorySize, CONV_SMEM);
    int total = Ma + Mr;
    int G = 296;                               // 2 CTAs/SM on 148 SMs
    int Ga = (int)((long long)G * Ma / total);
    if (Ga < 1) Ga = 1; if (Ga > G - 1) Ga = G - 1;
    int Gr = G - Ga;
    conv_kernel<<<G, 256, CONV_SMEM>>>(featA, coors_agent, ownerA, Ma,
                                       featR, coors_rg,    ownerR, Mr,
                                       conv_w, out, Ga, Gr);
}

// round 15
// speedup vs baseline: 1.1687x; 1.0501x over previous
#include <cuda_runtime.h>
#include <cuda_bf16.h>
#include <cstdint>

// ---------------- problem constants ----------------
#define NXC 256
#define NYC 256
#define BC  8
#define CO  32

__device__ __constant__ float c_VX    = 0.3125f;          // 1/3.2
__device__ __constant__ float c_VY    = 0.3125f;
__device__ __constant__ float c_XOFF  = -39.84375f;       // VX/2 + X_MIN
__device__ __constant__ float c_YOFF  = -19.84375f;       // VY/2 + Y_MIN

// ---------------- scratch (device globals, zero-init at load) ----------------
__device__ float g_featA[60000 * 64];
__device__ float g_featR[80000 * 64];
__device__ int   g_ownerA[BC * NYC * NXC];
__device__ int   g_ownerR[BC * NYC * NXC];

// ---------------- packed f32x2 helpers (FFMA2 via PTX, sm_100+) -------------
typedef unsigned long long ull;

__device__ __forceinline__ ull pack2(float lo, float hi) {
    ull r; asm("mov.b64 %0, {%1,%2};" : "=l"(r) : "f"(lo), "f"(hi)); return r;
}
__device__ __forceinline__ void fma2(ull& d, ull a, ull b) {
    asm("fma.rn.f32x2 %0, %1, %2, %3;" : "=l"(d) : "l"(a), "l"(b), "l"(d));
}
__device__ __forceinline__ float2 unpack2(ull v) {
    float2 r; asm("mov.b64 {%0,%1}, %2;" : "=f"(r.x), "=f"(r.y) : "l"(v)); return r;
}
__device__ __forceinline__ void red_add_v2(float* p, float x, float y) {
    asm volatile("red.global.add.v2.f32 [%0], {%1,%2};" :: "l"(p), "f"(x), "f"(y) : "memory");
}

// ============================================================================
// VFE multi-pillar warp body, software-pipelined.
// ONE WARP handles NP consecutive pillars; folded weights built once per warp.
// Voxel rows are loaded as ONE LDG.128 per lane; the NEXT pillar's float4 is
// prefetched into registers while the current pillar computes.
// Lane owns output-dim pair d = (2*lane, 2*lane+1).
//   dot_p = sum_{c<C} v_pc * we_c + K     (cluster/center channels folded)
// out = max(0, max_{p<np} dot_p). Owner resolution (last idx wins) fused.
// ============================================================================
template <int P, int C, int NP>
__device__ __forceinline__ void vfe_multi(
    const float* __restrict__ voxels, const int* __restrict__ coors,
    const int* __restrict__ nump, const float* __restrict__ W,
    const float* __restrict__ bias, float* __restrict__ outf,
    int* __restrict__ owner, int base, int M, ull* __restrict__ sraw)
{
    constexpr int PC  = P * C;
    constexpr int PC4 = PC / 4;       // 25 (agent) or 24 (rg)
    int lane = threadIdx.x & 31;

    // ---- per-warp weight fold (amortized over NP pillars) ----
    float2 wc[5];                       // channels C..C+4
#pragma unroll
    for (int c = 0; c < 5; ++c) wc[c] = *(const float2*)(W + (C + c) * 64 + 2 * lane);
    float2 bs = *(const float2*)(bias + 2 * lane);

    ull we2[C];
#pragma unroll
    for (int c = 0; c < C; ++c) {
        float2 w = *(const float2*)(W + c * 64 + 2 * lane);
        if (c == 0) { w.x += wc[0].x + wc[3].x;  w.y += wc[0].y + wc[3].y; }
        if (c == 1) { w.x += wc[1].x + wc[4].x;  w.y += wc[1].y + wc[4].y; }
        if (c == 2) { w.x += wc[2].x;            w.y += wc[2].y; }
        we2[c] = pack2(w.x, w.y);
    }

    const float* srawf = (const float*)sraw;   // lo half of each dup pair

    // prologue prefetch: pillar 'base' row into registers (LDG.128)
    float4 nv = make_float4(0.f, 0.f, 0.f, 0.f);
    if (base < M && lane < PC4)
        nv = *(const float4*)(voxels + (size_t)base * PC + lane * 4);

#pragma unroll 1
    for (int t = 0; t < NP; ++t) {
        int i = base + t;                 // warp-uniform
        if (i >= M) return;

        // stage current pillar from prefetch regs (duplicated pairs)
        if (lane < PC4) {
            sraw[lane * 4 + 0] = pack2(nv.x, nv.x);
            sraw[lane * 4 + 1] = pack2(nv.y, nv.y);
            sraw[lane * 4 + 2] = pack2(nv.z, nv.z);
            sraw[lane * 4 + 3] = pack2(nv.w, nv.w);
        }
        int np = nump[i];                 // 1..P
        __syncwarp();

        // prefetch next pillar while this one computes
        if (t + 1 < NP && i + 1 < M && lane < PC4)
            nv = *(const float4*)(voxels + (size_t)(i + 1) * PC + lane * 4);

        // mean over first np points (P <= 32) via bfly reduction
        float sx = 0.f, sy = 0.f, sz = 0.f;
        if (lane < np) {
            sx = srawf[(lane * C + 0) * 2];
            sy = srawf[(lane * C + 1) * 2];
            sz = srawf[(lane * C + 2) * 2];
        }
#pragma unroll
        for (int o = 16; o; o >>= 1) {
            sx += __shfl_xor_sync(0xffffffffu, sx, o);
            sy += __shfl_xor_sync(0xffffffffu, sy, o);
            sz += __shfl_xor_sync(0xffffffffu, sz, o);
        }
        float inv = 1.f / (float)np;
        float mx = sx * inv, my = sy * inv, mz = sz * inv;

        int cb = coors[3 * i], cy = coors[3 * i + 1], cx = coors[3 * i + 2];
        if (lane == 0) atomicMax(&owner[(cb * NYC + cy) * NXC + cx], i + 1);
        float xo = (float)cx * c_VX + c_XOFF;
        float yo = (float)cy * c_VY + c_YOFF;

        float Kx = bs.x - mx * wc[0].x - my * wc[1].x - mz * wc[2].x
                        - xo * wc[3].x - yo * wc[4].x;
        float Ky = bs.y - mx * wc[0].y - my * wc[1].y - mz * wc[2].y
                        - xo * wc[3].y - yo * wc[4].y;
        ull K2 = pack2(Kx, Ky);

        float a0 = 0.f, a1 = 0.f, b0 = 0.f, b1 = 0.f;
        int p = 0;
        for (; p + 2 <= np; p += 2) {
            ull d2 = K2, e2 = K2;
            const ull* r0 = &sraw[p * C];
#pragma unroll
            for (int c = 0; c < C; ++c) {
                fma2(d2, r0[c],     we2[c]);
                fma2(e2, r0[C + c], we2[c]);
            }
            float2 u = unpack2(d2), w = unpack2(e2);
            a0 = fmaxf(a0, u.x); a1 = fmaxf(a1, u.y);
            b0 = fmaxf(b0, w.x); b1 = fmaxf(b1, w.y);
        }
        if (p < np) {
            ull d2 = K2;
            const ull* r0 = &sraw[p * C];
#pragma unroll
            for (int c = 0; c < C; ++c) fma2(d2, r0[c], we2[c]);
            float2 u = unpack2(d2);
            a0 = fmaxf(a0, u.x); a1 = fmaxf(a1, u.y);
        }
        float2 res = make_float2(fmaxf(a0, b0), fmaxf(a1, b1));
        *(float2*)(outf + (size_t)i * 64 + 2 * lane) = res;
        __syncwarp();                     // protect sraw before next staging
    }
}

// ============================================================================
// Fused prep kernel: [init blocks | VFE agent blocks | VFE rg blocks]
// 256 threads = 8 warps; each warp handles NPIL consecutive pillars.
// ============================================================================
#define INITB 1024
#define NPIL  8

__global__ __launch_bounds__(256) void prep_kernel(
    const float* voxA, const int* cA, const int* npA, const float* wA, const float* bA,
    const float* voxR, const int* cR, const int* npR, const float* wR, const float* bR,
    float* featA, float* featR, int* ownerA, int* ownerR, int Ma, int Mr, int blkA,
    float4* out4, const float* __restrict__ cb, int n4)
{
    __shared__ __align__(16) ull sraw[8][100];   // max P*C = 100

    int bid = blockIdx.x;
    if (bid < INITB) {
        for (int i = bid * 256 + threadIdx.x; i < n4; i += INITB * 256) {
            int c = (i * 4) & (CO - 1);
            out4[i] = make_float4(cb[c], cb[c + 1], cb[c + 2], cb[c + 3]);
        }
        return;
    }
    int warp = threadIdx.x >> 5;
    int rel = bid - INITB;
    if (rel < blkA) {
        int base = (rel * 8 + warp) * NPIL;
        vfe_multi<20, 5, NPIL>(voxA, cA, npA, wA, bA, featA, ownerA, base, Ma, sraw[warp]);
    } else {
        int base = ((rel - blkA) * 8 + warp) * NPIL;
        vfe_multi<32, 3, NPIL>(voxR, cR, npR, wR, bR, featR, ownerR, base, Mr, sraw[warp]);
    }
}

// ============================================================================
// Fused sparse scatter-conv (R6 inner loop), software-pipelined staging.
// Block 256 thr (8 warps), T=8 pillars/warp. Lane: c2=2*(lane&15) co-pair,
// h=lane>>4 pillar parity. Next iteration's feats/cell/owner are prefetched
// into registers right after the current STS, so the 64-ci FFMA2 loop covers
// the global-load latency. Weights: sw[tap][ci][co], 9 LDS.64/ci. Features:
// sf[warp][ci][t] stride 9 (conflict-free). Epilogue: red.global.add.v2.f32.
// smem: 72 KB weights + 18 KB features = 90 KB -> 2 CTA/SM.
// ============================================================================
#define CONV_SMEM (9 * 64 * 32 * 4 + 8 * 64 * 9 * 4)

struct ConvPrefetch {
    float f0[8], f1[8];
    int   cell[4];
    bool  ok[4];
};

__device__ __forceinline__ void conv_prefetch(
    ConvPrefetch& pf, int b, int M, int lane, int h,
    const float* __restrict__ feats, const int* __restrict__ coors,
    const int* __restrict__ owner)
{
#pragma unroll
    for (int t = 0; t < 8; ++t) {
        int i = b + t;
        float f0 = 0.f, f1 = 0.f;
        if (i < M) {
            f0 = feats[(size_t)i * 64 + lane];
            f1 = feats[(size_t)i * 64 + 32 + lane];
        }
        pf.f0[t] = f0; pf.f1[t] = f1;
        if ((t & 1) == h) {
            int tp = t >> 1;
            bool ok = false; int cell = 0;
            if (i < M) {
                int bb = coors[3 * i], y = coors[3 * i + 1], x = coors[3 * i + 2];
                cell = (bb * NYC + y) * NXC + x;
                ok = (owner[cell] == i + 1);
            }
            pf.cell[tp] = cell; pf.ok[tp] = ok;
        }
    }
}

__global__ __launch_bounds__(256, 2) void conv_kernel(
    const float* __restrict__ fA, const int* __restrict__ cA, const int* __restrict__ oA, int Ma,
    const float* __restrict__ fR, const int* __restrict__ cR, const int* __restrict__ oR, int Mr,
    const float* __restrict__ conv_w, float* __restrict__ out, int Ga, int Gr)
{
    extern __shared__ __align__(16) float smem[];
    float* sw = smem;                 // [tap][ci][co]
    float* sf = smem + 9 * 64 * 32;   // [warp][ci][t(stride 9)]

    bool isA = (int)blockIdx.x < Ga;
    const float* feats = isA ? fA : fR;
    const int*   coors = isA ? cA : cR;
    const int*   owner = isA ? oA : oR;
    int M      = isA ? Ma : Mr;
    int ci_off = isA ? 0 : 64;
    int nblk   = isA ? Ga : Gr;
    int blk    = isA ? blockIdx.x : blockIdx.x - Ga;

    int tid = threadIdx.x;
    for (int k = tid; k < 9 * 64 * 32; k += 256) {
        int tap = k >> 11, rem = k & 2047;              // rem = ci*32+co
        sw[k] = conv_w[(tap * 128 + ci_off + (rem >> 5)) * 32 + (rem & 31)];
    }
    __syncthreads();

    int warp = tid >> 5, lane = tid & 31;
    int h = lane >> 4;                 // pillar parity this lane owns
    int c2 = (lane & 15) * 2;          // co pair
    float* sfw = sf + warp * (64 * 9);

    int stride = nblk * 8 * 8;         // blocks * warps * T
    int base = (blk * 8 + warp) * 8;

    ConvPrefetch pf;
    if (base < M) conv_prefetch(pf, base, M, lane, h, feats, coors, owner);

    for (; base < M; base += stride) {
        // stage current iteration from prefetch regs
#pragma unroll
        for (int t = 0; t < 8; ++t) {
            sfw[lane * 9 + t]        = pf.f0[t];   // stride 9 -> conflict-free
            sfw[(lane + 32) * 9 + t] = pf.f1[t];
        }
        int  ccell[4]; bool cok[4];
#pragma unroll
        for (int tp = 0; tp < 4; ++tp) { ccell[tp] = pf.cell[tp]; cok[tp] = pf.ok[tp]; }
        __syncwarp();

        // prefetch next iteration (latency hidden by the ci loop below)
        int nb = base + stride;
        if (nb < M) conv_prefetch(pf, nb, M, lane, h, feats, coors, owner);

        ull acc[4][9];
#pragma unroll
        for (int tp = 0; tp < 4; ++tp)
#pragma unroll
            for (int k = 0; k < 9; ++k) acc[tp][k] = 0ULL;

#pragma unroll 4
        for (int ci = 0; ci < 64; ++ci) {
            ull f2[4];
#pragma unroll
            for (int tp = 0; tp < 4; ++tp) {
                float fv = sfw[ci * 9 + 2 * tp + h];
                f2[tp] = pack2(fv, fv);
            }
            const float* wrow = sw + ci * 32 + c2;
#pragma unroll
            for (int tap = 0; tap < 9; ++tap) {
                ull w2 = *reinterpret_cast<const ull*>(wrow + tap * 2048);  // LDS.64 pair
#pragma unroll
                for (int tp = 0; tp < 4; ++tp) fma2(acc[tp][tap], f2[tp], w2);
            }
        }

#pragma unroll
        for (int tp = 0; tp < 4; ++tp) {
            if (!cok[tp]) continue;
            int cell = ccell[tp];
            int x = cell & 255, y = (cell >> 8) & 255, bt = cell >> 16;
#pragma unroll
            for (int ky = 0; ky < 3; ++ky) {
                int oy = y + 1 - ky;
                if ((unsigned)oy >= NYC) continue;
                size_t rb = ((size_t)bt * NYC + oy) * NXC;
#pragma unroll
                for (int kx = 0; kx < 3; ++kx) {
                    int ox = x + 1 - kx;
                    if ((unsigned)ox >= NXC) continue;
                    float2 v2 = unpack2(acc[tp][ky * 3 + kx]);
                    red_add_v2(out + (rb + ox) * 32 + c2, v2.x, v2.y);
                }
            }
        }
        __syncwarp();   // all lanes done reading sfw before next overwrite
    }
}

// ============================================================================
// launch
// ============================================================================
extern "C" void kernel_launch(void* const* d_in, const int* in_sizes, int n_in,
                              void* d_out, int out_size)
{
    const float* voxels_agent = (const float*)d_in[0];
    const int*   coors_agent  = (const int*)  d_in[1];
    const int*   np_agent     = (const int*)  d_in[2];
    const float* voxels_rg    = (const float*)d_in[3];
    const int*   coors_rg     = (const int*)  d_in[4];
    const int*   np_rg        = (const int*)  d_in[5];
    const float* w_agent      = (const float*)d_in[6];
    const float* b_agent      = (const float*)d_in[7];
    const float* w_rg         = (const float*)d_in[8];
    const float* b_rg         = (const float*)d_in[9];
    const float* conv_w       = (const float*)d_in[10];
    const float* conv_b       = (const float*)d_in[11];

    int Ma = in_sizes[0] / (20 * 5);
    int Mr = in_sizes[3] / (32 * 3);
    float* out = (float*)d_out;

    float *featA, *featR;
    int   *ownerA, *ownerR;
    cudaGetSymbolAddress((void**)&featA,  g_featA);
    cudaGetSymbolAddress((void**)&featR,  g_featR);
    cudaGetSymbolAddress((void**)&ownerA, g_ownerA);
    cudaGetSymbolAddress((void**)&ownerR, g_ownerR);

    // 1) fused init + pipelined multi-pillar VFE + owner resolution
    int n4 = out_size / 4;
    int blkA = (Ma + 8 * NPIL - 1) / (8 * NPIL);
    int blkR = (Mr + 8 * NPIL - 1) / (8 * NPIL);
    prep_kernel<<<INITB + blkA + blkR, 256>>>(
        voxels_agent, coors_agent, np_agent, w_agent, b_agent,
        voxels_rg, coors_rg, np_rg, w_rg, b_rg,
        featA, featR, ownerA, ownerR, Ma, Mr, blkA,
        (float4*)out, conv_b, n4);

    // 2) fused sparse scatter-conv (both sets, all 9 taps, pipelined staging)
    cudaFuncSetAttribute(conv_kernel, cudaFuncAttributeMaxDynamicSharedMemorySize, CONV_SMEM);
    int total = Ma + Mr;
    int G = 296;                               // 2 CTAs/SM on 148 SMs
    int Ga = (int)((long long)G * Ma / total);
    if (Ga < 1) Ga = 1; if (Ga > G - 1) Ga = G - 1;
    int Gr = G - Ga;
    conv_kernel<<<G, 256, CONV_SMEM>>>(featA, coors_agent, ownerA, Ma,
                                       featR, coors_rg,    ownerR, Mr,
                                       conv_w, out, Ga, Gr);
}